// round 3
// baseline (speedup 1.0000x reference)
#include <cuda_runtime.h>
#include <math.h>
#include <float.h>

// WaveNet autoregressive generation, sm_103a.
// B=128 rows, T steps, 30 layers (dilations 1..512 x3 blocks), C=64, S=256, V=256.
// One CTA owns 2 batch rows for the full generation (rows are independent:
// per-row argmax feedback, per-row queues) -> single kernel launch, no grid sync.
// Weights (5MB, L2-resident) are loaded once per CTA-step as float4 and reused
// for both rows in registers. Dilation queues live in a static __device__ ring;
// the (t >= d) guard makes replays deterministic without re-zeroing.

#define NLAYER 30
#define CCH 64
#define SCH 256
#define VV  256
#define BB  128
#define RING_PER_ROW 3069   // 3 * (2^10 - 1) queue slots, 64 floats each

__device__ float g_ring[(size_t)BB * RING_PER_ROW * CCH];  // ~100.6 MB static scratch

// Partial mat-vec for 2 rows: 4 consecutive output channels (float4 weight rows),
// KCNT inner-dim elements starting at kb. Accumulates into o0 (row0) / o1 (row1).
template <int KCNT>
__device__ __forceinline__ void mm_part(const float* __restrict__ act0,
                                        const float* __restrict__ act1,
                                        const float4* __restrict__ W,
                                        int wstride, int kb, int jq,
                                        float4& o0, float4& o1) {
#pragma unroll
    for (int kc = 0; kc < KCNT; kc += 4) {
        float a0[4], a1[4];
        *(float4*)a0 = *(const float4*)&act0[kb + kc];
        *(float4*)a1 = *(const float4*)&act1[kb + kc];
#pragma unroll
        for (int u = 0; u < 4; u++) {
            float4 w = W[(size_t)(kb + kc + u) * wstride + jq];
            o0.x = fmaf(a0[u], w.x, o0.x);
            o0.y = fmaf(a0[u], w.y, o0.y);
            o0.z = fmaf(a0[u], w.z, o0.z);
            o0.w = fmaf(a0[u], w.w, o0.w);
            o1.x = fmaf(a1[u], w.x, o1.x);
            o1.y = fmaf(a1[u], w.y, o1.y);
            o1.z = fmaf(a1[u], w.z, o1.z);
            o1.w = fmaf(a1[u], w.w, o1.w);
        }
    }
}

__global__ __launch_bounds__(256)
void wavenet_kernel(const int* __restrict__ seed,
                    const float* __restrict__ emb,     // (V, C)
                    const float* __restrict__ kern,    // (L, 2, C, 2C)
                    const float* __restrict__ cbias,   // (L, 2C)
                    const float* __restrict__ rw,      // (L, C, C)
                    const float* __restrict__ rb,      // (L, C)
                    const float* __restrict__ sw,      // (L, C, S)
                    const float* __restrict__ sb,      // (L, S)
                    const float* __restrict__ ow0,     // (S, V)
                    const float* __restrict__ ob0,     // (V)
                    const float* __restrict__ ow1,     // (V, V)
                    const float* __restrict__ ob1,     // (V)
                    float* __restrict__ out,
                    int T, long long samp_off, long long logit_off, int mode)
{
    __shared__ __align__(16) float sx[2][CCH];       // current layer input x
    __shared__ __align__(16) float sxl[2][CCH];      // dequeued x_last
    __shared__ __align__(16) float sg[2][CCH];       // gated activation
    __shared__ __align__(16) float sskip[2][SCH];    // skip accumulator
    __shared__ __align__(16) float sh0[2][SCH];      // relu(skip @ W0 + b0)
    __shared__ __align__(16) float slg[2][VV];       // logits
    __shared__ __align__(16) float scp[8][2][128];   // conv k-split partials
    __shared__ __align__(16) float srp[16][2][64];   // res  k-split partials
    __shared__ __align__(16) float ssp[4][2][256];   // skip/out k-split partials
    __shared__ int snidx[2];

    const int tid = threadIdx.x;
    const int row0 = blockIdx.x * 2;

    if (tid < 2) snidx[tid] = seed[row0 + tid];
    __syncthreads();

#pragma unroll 1
    for (int t = 0; t < T; t++) {
        // ---- step head: embedding lookup + zero skip ----
        if (tid < 128) {
            int r = tid >> 6, c = tid & 63;
            sx[r][c] = emb[(size_t)snidx[r] * CCH + c];
        }
        sskip[0][tid] = 0.f;
        sskip[1][tid] = 0.f;
        __syncthreads();

        // ---- 30 residual layers ----
#pragma unroll 1
        for (int i = 0; i < NLAYER; i++) {
            const int lb = i % 10;
            const int d = 1 << lb;
            const long long off = (long long)(i / 10) * 1023 + (d - 1);

            // queue pop (oldest == written d steps ago) + push current x
            if (tid < 128) {
                int r = tid >> 6, c = tid & 63;
                size_t idx = ((size_t)(row0 + r) * RING_PER_ROW + (size_t)off + (t & (d - 1))) * CCH + c;
                float xl = (t >= d) ? g_ring[idx] : 0.f;
                sxl[r][c] = xl;
                g_ring[idx] = sx[r][c];
            }
            __syncthreads();

            // conv: h = x_last@K0 + x@K1 ; 256 thr = 32 j-quads x 8 k-splits of 8
            {
                int jq = tid & 31, ks = tid >> 5, kb = ks * 8;
                const float4* K0 = (const float4*)(kern + (size_t)(i * 2) * CCH * 128);
                const float4* K1 = (const float4*)(kern + (size_t)(i * 2 + 1) * CCH * 128);
                float4 o0 = {0, 0, 0, 0}, o1 = {0, 0, 0, 0};
                mm_part<8>(sxl[0], sxl[1], K0, 32, kb, jq, o0, o1);
                mm_part<8>(sx[0],  sx[1],  K1, 32, kb, jq, o0, o1);
                *(float4*)&scp[ks][0][4 * jq] = o0;
                *(float4*)&scp[ks][1][4 * jq] = o1;
            }
            __syncthreads();

            // combine partials + gate: g = tanh(h[:64]) * sigmoid(h[64:])
            if (tid < 128) {
                int r = tid >> 6, c = tid & 63;
                float ht = cbias[i * 128 + c];
                float hs = cbias[i * 128 + 64 + c];
#pragma unroll
                for (int ks = 0; ks < 8; ks++) {
                    ht += scp[ks][r][c];
                    hs += scp[ks][r][c + 64];
                }
                sg[r][c] = tanhf(ht) * (1.f / (1.f + expf(-hs)));
            }
            __syncthreads();

            // res partials: 16 j-quads x 16 k-splits of 4
            {
                int jq = tid & 15, ks = tid >> 4, kb = ks * 4;
                const float4* RW = (const float4*)(rw + (size_t)i * CCH * CCH);
                float4 o0 = {0, 0, 0, 0}, o1 = {0, 0, 0, 0};
                mm_part<4>(sg[0], sg[1], RW, 16, kb, jq, o0, o1);
                *(float4*)&srp[ks][0][4 * jq] = o0;
                *(float4*)&srp[ks][1][4 * jq] = o1;
            }
            // skip partials: 64 j-quads x 4 k-splits of 16
            {
                int jq = tid & 63, ks = tid >> 6, kb = ks * 16;
                const float4* SW = (const float4*)(sw + (size_t)i * CCH * SCH);
                float4 o0 = {0, 0, 0, 0}, o1 = {0, 0, 0, 0};
                mm_part<16>(sg[0], sg[1], SW, 64, kb, jq, o0, o1);
                *(float4*)&ssp[ks][0][4 * jq] = o0;
                *(float4*)&ssp[ks][1][4 * jq] = o1;
            }
            __syncthreads();

            // x += g@res_w + res_b
            if (tid < 128) {
                int r = tid >> 6, c = tid & 63;
                float v = sx[r][c] + rb[i * 64 + c];
#pragma unroll
                for (int ks = 0; ks < 16; ks++) v += srp[ks][r][c];
                sx[r][c] = v;
            }
            // skip += g@skip_w + skip_b
            {
                float bias = sb[i * 256 + tid];
                float s0 = bias, s1 = bias;
#pragma unroll
                for (int ks = 0; ks < 4; ks++) {
                    s0 += ssp[ks][0][tid];
                    s1 += ssp[ks][1][tid];
                }
                sskip[0][tid] += s0;
                sskip[1][tid] += s1;
            }
            __syncthreads();
        }

        // ---- output head ----
        sskip[0][tid] = fmaxf(sskip[0][tid], 0.f);
        sskip[1][tid] = fmaxf(sskip[1][tid], 0.f);
        __syncthreads();

        // h0 = relu(skip @ out_w0 + b0): 64 j-quads x 4 k-splits of 64
        {
            int jq = tid & 63, ks = tid >> 6, kb = ks * 64;
            const float4* W = (const float4*)ow0;
            float4 o0 = {0, 0, 0, 0}, o1 = {0, 0, 0, 0};
            mm_part<64>(sskip[0], sskip[1], W, 64, kb, jq, o0, o1);
            *(float4*)&ssp[ks][0][4 * jq] = o0;
            *(float4*)&ssp[ks][1][4 * jq] = o1;
        }
        __syncthreads();
        {
            float v0 = ob0[tid], v1 = ob0[tid];
#pragma unroll
            for (int ks = 0; ks < 4; ks++) {
                v0 += ssp[ks][0][tid];
                v1 += ssp[ks][1][tid];
            }
            sh0[0][tid] = fmaxf(v0, 0.f);
            sh0[1][tid] = fmaxf(v1, 0.f);
        }
        __syncthreads();

        // logits = h0 @ out_w1 + b1
        {
            int jq = tid & 63, ks = tid >> 6, kb = ks * 64;
            const float4* W = (const float4*)ow1;
            float4 o0 = {0, 0, 0, 0}, o1 = {0, 0, 0, 0};
            mm_part<64>(sh0[0], sh0[1], W, 64, kb, jq, o0, o1);
            *(float4*)&ssp[ks][0][4 * jq] = o0;
            *(float4*)&ssp[ks][1][4 * jq] = o1;
        }
        __syncthreads();
        {
            float v0 = ob1[tid], v1 = ob1[tid];
#pragma unroll
            for (int ks = 0; ks < 4; ks++) {
                v0 += ssp[ks][0][tid];
                v1 += ssp[ks][1][tid];
            }
            slg[0][tid] = v0;
            slg[1][tid] = v1;
            if (mode & 2) {
                out[logit_off + ((size_t)(row0 + 0) * T + t) * VV + tid] = v0;
                out[logit_off + ((size_t)(row0 + 1) * T + t) * VV + tid] = v1;
            }
        }
        __syncthreads();

        // argmax per row (first-max-index tie rule, matching jnp.argmax)
        if (tid < 64) {
            int r = tid >> 5, lane = tid & 31;
            float bv = -FLT_MAX;
            int bi = 0;
#pragma unroll
            for (int jj = 0; jj < 8; jj++) {
                int j = lane + jj * 32;
                float v = slg[r][j];
                if (v > bv) { bv = v; bi = j; }
            }
#pragma unroll
            for (int o = 16; o > 0; o >>= 1) {
                float ov = __shfl_down_sync(0xffffffffu, bv, o);
                int   oi = __shfl_down_sync(0xffffffffu, bi, o);
                if (ov > bv || (ov == bv && oi < bi)) { bv = ov; bi = oi; }
            }
            if (lane == 0) {
                snidx[r] = bi;
                if (mode & 1) out[samp_off + (size_t)(row0 + r) * T + t] = (float)bi;
                if (mode & 4) ((int*)out)[(size_t)(row0 + r) * T + t] = bi;
            }
        }
        __syncthreads();
    }
}

extern "C" void kernel_launch(void* const* d_in, const int* in_sizes, int n_in,
                              void* d_out, int out_size) {
    const int*   seed  = (const int*)d_in[0];
    const float* emb   = (const float*)d_in[1];
    const float* kern  = (const float*)d_in[2];
    const float* cbias = (const float*)d_in[3];
    const float* rw    = (const float*)d_in[4];
    const float* rb    = (const float*)d_in[5];
    const float* sw    = (const float*)d_in[6];
    const float* sb    = (const float*)d_in[7];
    const float* ow0   = (const float*)d_in[8];
    const float* ob0   = (const float*)d_in[9];
    const float* ow1   = (const float*)d_in[10];
    const float* ob1   = (const float*)d_in[11];
    (void)in_sizes; (void)n_in;

    // Output layout inferred from out_size:
    //   B*T*(V+1): flattened tuple (samples first, then logits) as float
    //   B*T*V    : logits only (float)
    //   B*T      : samples only (int32)
    int T, mode;
    long long samp_off = 0, logit_off = 0;
    if (out_size % (BB * (VV + 1)) == 0) {
        T = out_size / (BB * (VV + 1));
        mode = 1 | 2;                       // float samples + logits
        samp_off = 0;
        logit_off = (long long)BB * T;
    } else if (out_size % (BB * VV) == 0) {
        T = out_size / (BB * VV);
        mode = 2;                           // logits only
        logit_off = 0;
    } else {
        T = out_size / BB;
        mode = 4;                           // int32 samples only
    }

    wavenet_kernel<<<BB / 2, 256>>>(seed, emb, kern, cbias, rw, rb, sw, sb,
                                    ow0, ob0, ow1, ob1,
                                    (float*)d_out, T, samp_off, logit_off, mode);
}

// round 4
// speedup vs baseline: 1.7903x; 1.7903x over previous
#include <cuda_runtime.h>
#include <math.h>
#include <float.h>

// WaveNet autoregressive generation, sm_103a — round 3: latency-hiding rewrite.
// 64 CTAs x 2 rows (L2-traffic-optimal R=2), 256 threads.
// All weight loads are software-pipelined into register buffers (wk/wr/ws) and
// issued one phase ahead of use, so L2 latency overlaps compute + barriers.
// Dilation-queue pops are prefetched one layer ahead (they depend only on t).

#define NLAYER 30
#define CCH 64
#define SCH 256
#define VV  256
#define BB  128
#define RING_PER_ROW 3069   // 3 * (2^10 - 1) slots, 64 floats each

__device__ float g_ring[(size_t)BB * RING_PER_ROW * CCH];  // ~100.6 MB scratch

// Load N float4 weight rows (stride wstride4 float4s) at column-quad jq into regs.
template<int N>
__device__ __forceinline__ void wload(float4* dst, const float* __restrict__ W,
                                      int wstride4, int kb, int jq) {
    const float4* W4 = (const float4*)W;
#pragma unroll
    for (int u = 0; u < N; u++)
        dst[u] = W4[(size_t)(kb + u) * wstride4 + jq];
}

// FMA N k-steps from a register weight buffer; activations broadcast from smem.
template<int N>
__device__ __forceinline__ void mmacc(const float* __restrict__ a0,
                                      const float* __restrict__ a1,
                                      const float4* w, int kb,
                                      float4& o0, float4& o1) {
#pragma unroll
    for (int u = 0; u < N; u++) {
        float x0 = a0[kb + u], x1 = a1[kb + u];
        o0.x = fmaf(x0, w[u].x, o0.x);
        o0.y = fmaf(x0, w[u].y, o0.y);
        o0.z = fmaf(x0, w[u].z, o0.z);
        o0.w = fmaf(x0, w[u].w, o0.w);
        o1.x = fmaf(x1, w[u].x, o1.x);
        o1.y = fmaf(x1, w[u].y, o1.y);
        o1.z = fmaf(x1, w[u].z, o1.z);
        o1.w = fmaf(x1, w[u].w, o1.w);
    }
}

// Inline load+FMA (for head remainders where prefetch regs ran out).
template<int N>
__device__ __forceinline__ void mmld(const float* __restrict__ a0,
                                     const float* __restrict__ a1,
                                     const float* __restrict__ W,
                                     int wstride4, int kb, int jq,
                                     float4& o0, float4& o1) {
    const float4* W4 = (const float4*)W;
#pragma unroll
    for (int u = 0; u < N; u++) {
        float4 w = W4[(size_t)(kb + u) * wstride4 + jq];
        float x0 = a0[kb + u], x1 = a1[kb + u];
        o0.x = fmaf(x0, w.x, o0.x);
        o0.y = fmaf(x0, w.y, o0.y);
        o0.z = fmaf(x0, w.z, o0.z);
        o0.w = fmaf(x0, w.w, o0.w);
        o1.x = fmaf(x1, w.x, o1.x);
        o1.y = fmaf(x1, w.y, o1.y);
        o1.z = fmaf(x1, w.z, o1.z);
        o1.w = fmaf(x1, w.w, o1.w);
    }
}

__global__ __launch_bounds__(256, 1)
void wavenet_kernel(const int* __restrict__ seed,
                    const float* __restrict__ emb,     // (V, C)
                    const float* __restrict__ kern,    // (L, 2, C, 2C)
                    const float* __restrict__ cbias,   // (L, 2C)
                    const float* __restrict__ rw,      // (L, C, C)
                    const float* __restrict__ rb,      // (L, C)
                    const float* __restrict__ sw,      // (L, C, S)
                    const float* __restrict__ sb,      // (L, S)
                    const float* __restrict__ ow0,     // (S, V)
                    const float* __restrict__ ob0,     // (V)
                    const float* __restrict__ ow1,     // (V, V)
                    const float* __restrict__ ob1,     // (V)
                    float* __restrict__ out,
                    int T, long long samp_off, long long logit_off, int mode)
{
    __shared__ __align__(16) float sx[2][CCH];
    __shared__ __align__(16) float sxl[2][CCH];
    __shared__ __align__(16) float sg[2][CCH];
    __shared__ __align__(16) float sskip[2][SCH];
    __shared__ __align__(16) float sh0[2][SCH];
    __shared__ __align__(16) float slg[2][VV];
    __shared__ __align__(16) float scp[8][2][128];
    __shared__ __align__(16) float srp[16][2][64];
    __shared__ __align__(16) float ssp[4][2][256];
    __shared__ int snidx[2];

    const int tid = threadIdx.x;
    const int row0 = blockIdx.x * 2;

    // phase-specific thread mappings
    const int jqc = tid & 31, kbc = (tid >> 5) * 8;   // conv: 32 jquads x 8 ksplits
    const int ksc = tid >> 5;
    const int jqr = tid & 15, kbr = (tid >> 4) * 4;   // res : 16 jquads x 16 ksplits
    const int ksr = tid >> 4;
    const int jqs = tid & 63, kbs = (tid >> 6) * 16;  // skip: 64 jquads x 4 ksplits
    const int kss = tid >> 6;
    const int jqh = tid & 63, kbh = (tid >> 6) * 64;  // head: 64 jquads x 4 ksplits
    const int ksh = tid >> 6;
    const int r = tid >> 6, c = tid & 63;             // valid for tid<128

    float4 wk[16];  // conv K0|K1 prefetch (or head chunk 0..15)
    float4 wr[4];   // res prefetch
    float4 ws[16];  // skip prefetch (or head chunk 16..31)
    float  rpop = 0.f;

    if (tid < 2) snidx[tid] = seed[row0 + tid];

    // prefetch conv weights for (t=0, layer 0); rpop(layer0,t=0)=0 (t<d)
    wload<8>(wk,     kern,              32, kbc, jqc);
    wload<8>(wk + 8, kern + CCH * 128,  32, kbc, jqc);
    __syncthreads();

#pragma unroll 1
    for (int t = 0; t < T; t++) {
        // ---- step head: embedding lookup, seed sxl for layer 0, zero skip ----
        if (tid < 128) {
            sx[r][c] = emb[(size_t)snidx[r] * CCH + c];
            sxl[r][c] = rpop;
        }
        sskip[0][tid] = 0.f;
        sskip[1][tid] = 0.f;
        __syncthreads();

#pragma unroll 1
        for (int i = 0; i < NLAYER; i++) {
            const int d = 1 << (i % 10);
            const long long off = (long long)(i / 10) * 1023 + (d - 1);

            // ---- Phase A: conv FMA (prefetched wk) + ring push + wr/ws prefetch ----
            {
                float4 o0 = {0, 0, 0, 0}, o1 = {0, 0, 0, 0};
                mmacc<8>(sxl[0], sxl[1], wk,     kbc, o0, o1);
                mmacc<8>(sx[0],  sx[1],  wk + 8, kbc, o0, o1);
                *(float4*)&scp[ksc][0][4 * jqc] = o0;
                *(float4*)&scp[ksc][1][4 * jqc] = o1;
            }
            if (tid < 128) {
                size_t idx = ((size_t)(row0 + r) * RING_PER_ROW + (size_t)off
                              + (t & (d - 1))) * CCH + c;
                g_ring[idx] = sx[r][c];                 // push x_i (pop already done)
            }
            wload<4>(wr,  rw + (size_t)i * CCH * CCH,  16, kbr, jqr);
            wload<16>(ws, sw + (size_t)i * CCH * SCH,  64, kbs, jqs);
            __syncthreads();

            // ---- Phase B: gate + prefetch next conv weights & next queue pop ----
            if (i < NLAYER - 1) {
                const float* kn = kern + (size_t)(i + 1) * 2 * CCH * 128;
                wload<8>(wk,     kn,             32, kbc, jqc);
                wload<8>(wk + 8, kn + CCH * 128, 32, kbc, jqc);
                if (tid < 128) {
                    const int d2 = 1 << ((i + 1) % 10);
                    const long long off2 = (long long)((i + 1) / 10) * 1023 + (d2 - 1);
                    size_t idx2 = ((size_t)(row0 + r) * RING_PER_ROW + (size_t)off2
                                   + (t & (d2 - 1))) * CCH + c;
                    rpop = (t >= d2) ? g_ring[idx2] : 0.f;
                }
            } else {
                wload<16>(wk, ow0, 64, kbh, jqh);       // head W0 k-rows [kbh, kbh+16)
            }
            if (tid < 128) {
                float ht = cbias[i * 128 + c];
                float hs = cbias[i * 128 + 64 + c];
#pragma unroll
                for (int ks = 0; ks < 8; ks++) {
                    ht += scp[ks][r][c];
                    hs += scp[ks][r][c + 64];
                }
                sg[r][c] = tanhf(ht) * (1.f / (1.f + expf(-hs)));
            }
            __syncthreads();

            // ---- Phase C: res + skip FMA (prefetched wr/ws) ----
            {
                float4 o0 = {0, 0, 0, 0}, o1 = {0, 0, 0, 0};
                mmacc<4>(sg[0], sg[1], wr, kbr, o0, o1);
                *(float4*)&srp[ksr][0][4 * jqr] = o0;
                *(float4*)&srp[ksr][1][4 * jqr] = o1;
            }
            {
                float4 o0 = {0, 0, 0, 0}, o1 = {0, 0, 0, 0};
                mmacc<16>(sg[0], sg[1], ws, kbs, o0, o1);
                *(float4*)&ssp[kss][0][4 * jqs] = o0;
                *(float4*)&ssp[kss][1][4 * jqs] = o1;
            }
            __syncthreads();

            // ---- Phase D: combine (x update, skip accum, stage next sxl) ----
            if (tid < 128) {
                float v = sx[r][c] + rb[i * 64 + c];
#pragma unroll
                for (int ks = 0; ks < 16; ks++) v += srp[ks][r][c];
                sx[r][c] = v;
                if (i < NLAYER - 1) sxl[r][c] = rpop;
            }
            {
                float bias = sb[i * 256 + tid];
                float s0 = sskip[0][tid] + bias;
                float s1 = sskip[1][tid] + bias;
#pragma unroll
                for (int ks = 0; ks < 4; ks++) {
                    s0 += ssp[ks][0][tid];
                    s1 += ssp[ks][1][tid];
                }
                if (i == NLAYER - 1) { s0 = fmaxf(s0, 0.f); s1 = fmaxf(s1, 0.f); }
                sskip[0][tid] = s0;
                sskip[1][tid] = s1;
            }
            if (i == NLAYER - 1)
                wload<16>(ws, ow0, 64, kbh + 16, jqh);  // head W0 k-rows [kbh+16, kbh+32)
            __syncthreads();
        }

        // ---- head H1: h0_partial = relu(skip) @ out_w0  (32 k prefetched + 32 inline)
        {
            float4 o0 = {0, 0, 0, 0}, o1 = {0, 0, 0, 0};
            mmacc<16>(sskip[0], sskip[1], wk, kbh,      o0, o1);
            mmacc<16>(sskip[0], sskip[1], ws, kbh + 16, o0, o1);
            mmld<32>(sskip[0], sskip[1], ow0, 64, kbh + 32, jqh, o0, o1);
            *(float4*)&ssp[ksh][0][4 * jqh] = o0;
            *(float4*)&ssp[ksh][1][4 * jqh] = o1;
        }
        __syncthreads();

        // ---- head H2: h0 combine + relu; prefetch half of out_w1 ----
        wload<16>(wk, ow1, 64, kbh,      jqh);
        wload<16>(ws, ow1, 64, kbh + 16, jqh);
        {
            float v0 = ob0[tid], v1 = ob0[tid];
#pragma unroll
            for (int ks = 0; ks < 4; ks++) {
                v0 += ssp[ks][0][tid];
                v1 += ssp[ks][1][tid];
            }
            sh0[0][tid] = fmaxf(v0, 0.f);
            sh0[1][tid] = fmaxf(v1, 0.f);
        }
        __syncthreads();

        // ---- head H3: logits_partial = h0 @ out_w1 ----
        {
            float4 o0 = {0, 0, 0, 0}, o1 = {0, 0, 0, 0};
            mmacc<16>(sh0[0], sh0[1], wk, kbh,      o0, o1);
            mmacc<16>(sh0[0], sh0[1], ws, kbh + 16, o0, o1);
            mmld<32>(sh0[0], sh0[1], ow1, 64, kbh + 32, jqh, o0, o1);
            *(float4*)&ssp[ksh][0][4 * jqh] = o0;
            *(float4*)&ssp[ksh][1][4 * jqh] = o1;
        }
        __syncthreads();

        // ---- head H4: logits combine + store; prefetch (t+1, layer0) conv & pop ----
        wload<8>(wk,     kern,             32, kbc, jqc);
        wload<8>(wk + 8, kern + CCH * 128, 32, kbc, jqc);
        if (tid < 128) {   // layer 0 pop for t+1: slot is always base (d=1)
            size_t idx0 = ((size_t)(row0 + r) * RING_PER_ROW) * CCH + c;
            rpop = g_ring[idx0];
        }
        {
            float v0 = ob1[tid], v1 = ob1[tid];
#pragma unroll
            for (int ks = 0; ks < 4; ks++) {
                v0 += ssp[ks][0][tid];
                v1 += ssp[ks][1][tid];
            }
            slg[0][tid] = v0;
            slg[1][tid] = v1;
            if (mode & 2) {
                out[logit_off + ((size_t)(row0 + 0) * T + t) * VV + tid] = v0;
                out[logit_off + ((size_t)(row0 + 1) * T + t) * VV + tid] = v1;
            }
        }
        __syncthreads();

        // ---- head H5: argmax per row (first-max tie rule, matches jnp.argmax) ----
        if (tid < 64) {
            int rr = tid >> 5, lane = tid & 31;
            float bv = -FLT_MAX;
            int bi = 0;
#pragma unroll
            for (int jj = 0; jj < 8; jj++) {
                int j = lane + jj * 32;
                float v = slg[rr][j];
                if (v > bv) { bv = v; bi = j; }
            }
#pragma unroll
            for (int o = 16; o > 0; o >>= 1) {
                float ov = __shfl_down_sync(0xffffffffu, bv, o);
                int   oi = __shfl_down_sync(0xffffffffu, bi, o);
                if (ov > bv || (ov == bv && oi < bi)) { bv = ov; bi = oi; }
            }
            if (lane == 0) {
                snidx[rr] = bi;
                if (mode & 1) out[samp_off + (size_t)(row0 + rr) * T + t] = (float)bi;
                if (mode & 4) ((int*)out)[(size_t)(row0 + rr) * T + t] = bi;
            }
        }
        __syncthreads();
    }
}

extern "C" void kernel_launch(void* const* d_in, const int* in_sizes, int n_in,
                              void* d_out, int out_size) {
    const int*   seed  = (const int*)d_in[0];
    const float* emb   = (const float*)d_in[1];
    const float* kern  = (const float*)d_in[2];
    const float* cbias = (const float*)d_in[3];
    const float* rw    = (const float*)d_in[4];
    const float* rb    = (const float*)d_in[5];
    const float* sw    = (const float*)d_in[6];
    const float* sb    = (const float*)d_in[7];
    const float* ow0   = (const float*)d_in[8];
    const float* ob0   = (const float*)d_in[9];
    const float* ow1   = (const float*)d_in[10];
    const float* ob1   = (const float*)d_in[11];
    (void)in_sizes; (void)n_in;

    int T, mode;
    long long samp_off = 0, logit_off = 0;
    if (out_size % (BB * (VV + 1)) == 0) {
        T = out_size / (BB * (VV + 1));
        mode = 1 | 2;                       // float samples then logits
        samp_off = 0;
        logit_off = (long long)BB * T;
    } else if (out_size % (BB * VV) == 0) {
        T = out_size / (BB * VV);
        mode = 2;                           // logits only
        logit_off = 0;
    } else {
        T = out_size / BB;
        mode = 4;                           // int32 samples only
    }

    wavenet_kernel<<<BB / 2, 256>>>(seed, emb, kern, cbias, rw, rb, sw, sb,
                                    ow0, ob0, ow1, ob1,
                                    (float*)d_out, T, samp_off, logit_off, mode);
}